// round 4
// baseline (speedup 1.0000x reference)
#include <cuda_runtime.h>
#include <cuda_bf16.h>
#include <math_constants.h>
#include <cstdint>

// Problem constants
#define B_   16
#define L_   1024
#define D_   128
#define H_   8
#define HD_  16
#define ROWS (B_ * L_)          // 16384
#define LN_EPS 1e-5f

// ---------------- scratch (device globals; no allocation allowed) ----------
__device__ float g_qkv[ROWS * 3 * D_];
__device__ float g_ctx[ROWS * D_];
__device__ float g_x1 [ROWS * D_];
__device__ float g_ff1[ROWS * D_];
__device__ float g_ff2[ROWS * D_];
__device__ unsigned char g_mask8[(size_t)B_ * L_ * L_];
__device__ int g_mask_is_i32;

// ============================ helpers ======================================
__device__ __forceinline__ uint32_t smem_u32(const void* p) {
    uint32_t a;
    asm("{ .reg .u64 t; cvta.to.shared.u64 t, %1; cvt.u32.u64 %0, t; }"
        : "=r"(a) : "l"(p));
    return a;
}
__device__ __forceinline__ uint32_t pack_bf16x2(float e, float o) {
    uint32_t r;
    asm("cvt.rn.bf16x2.f32 %0, %1, %2;" : "=r"(r) : "f"(o), "f"(e));
    return r;
}
__device__ __forceinline__ float ex2f(float x) {
    float y; asm("ex2.approx.f32 %0, %1;" : "=f"(y) : "f"(x)); return y;
}
__device__ __forceinline__ float bfr(float x) {
    return __bfloat162float(__float2bfloat16_rn(x));
}
__device__ __forceinline__ float lo16f(uint32_t u) { return __uint_as_float(u << 16); }
__device__ __forceinline__ float hi16f(uint32_t u) { return __uint_as_float(u & 0xFFFF0000u); }

__device__ __forceinline__ void mma_bf16(float* c, const uint32_t* a, uint32_t b0, uint32_t b1) {
    asm volatile("mma.sync.aligned.m16n8k16.row.col.f32.bf16.bf16.f32 "
        "{%0,%1,%2,%3}, {%4,%5,%6,%7}, {%8,%9}, {%0,%1,%2,%3};"
        : "+f"(c[0]), "+f"(c[1]), "+f"(c[2]), "+f"(c[3])
        : "r"(a[0]), "r"(a[1]), "r"(a[2]), "r"(a[3]), "r"(b0), "r"(b1));
}
__device__ __forceinline__ void ldm_x4(uint32_t* r, uint32_t addr) {
    asm volatile("ldmatrix.sync.aligned.m8n8.x4.shared.b16 {%0,%1,%2,%3}, [%4];"
        : "=r"(r[0]), "=r"(r[1]), "=r"(r[2]), "=r"(r[3]) : "r"(addr));
}
__device__ __forceinline__ void ldm_x4_t(uint32_t* r, uint32_t addr) {
    asm volatile("ldmatrix.sync.aligned.m8n8.x4.trans.shared.b16 {%0,%1,%2,%3}, [%4];"
        : "=r"(r[0]), "=r"(r[1]), "=r"(r[2]), "=r"(r[3]) : "r"(addr));
}

// ---------------- mask dtype detection + canonicalization ------------------
__global__ void detect_mask_kernel(const unsigned char* __restrict__ m) {
    if (threadIdx.x == 0 && blockIdx.x == 0) {
        int i32like = 1;
        for (int i = 0; i < 4096; i += 4) {
            unsigned char b0 = m[i], b1 = m[i+1], b2 = m[i+2], b3 = m[i+3];
            if ((b1 | b2 | b3) != 0 || b0 > 1) { i32like = 0; break; }
        }
        g_mask_is_i32 = i32like;
    }
}
__global__ void convert_mask_kernel(const void* __restrict__ in, int n) {
    int i = blockIdx.x * blockDim.x + threadIdx.x;
    if (i >= n) return;
    unsigned char v;
    if (g_mask_is_i32) v = (((const int*)in)[i] != 0) ? 1 : 0;
    else               v = (((const unsigned char*)in)[i] != 0) ? 1 : 0;
    g_mask8[i] = v;
}

// ================= HMMA GEMM: C = A@B + bias (opt relu) ====================
// A [M,128] fp32, B [128,N] fp32 row-major. BM=64, BN=128, 256 threads.
// 3-term hi/lo bf16 split. Smem XOR-swizzled for conflict-free ldmatrix.
__global__ __launch_bounds__(256) void hmma_gemm_kernel(
    const float* __restrict__ A, const float* __restrict__ Bw,
    const float* __restrict__ bias, float* __restrict__ C,
    int N, int relu)
{
    __shared__ __align__(16) uint8_t sAh[64 * 128];
    __shared__ __align__(16) uint8_t sAl[64 * 128];
    __shared__ __align__(16) uint8_t sBh[2][64 * 128];   // [n-half][k-row][128B]
    __shared__ __align__(16) uint8_t sBl[2][64 * 128];

    const int tid  = threadIdx.x;
    const int lane = tid & 31;
    const int w    = tid >> 5;
    const int wm   = w & 3;            // m-warp: rows wm*16..+16
    const int wn   = w >> 2;           // n-warp: cols wn*64..+64
    const int m0   = blockIdx.y * 64;
    const int n0   = blockIdx.x * 128;

    const int rq = lane >> 2;
    const int d0 = (lane & 3) * 2;
    const int lr16  = lane & 15;
    const int lclog = lane >> 4;
    const int lm = lane >> 3, lr = lane & 7;

    float c[8][4];
    #pragma unroll
    for (int i = 0; i < 8; i++)
        #pragma unroll
        for (int j = 0; j < 4; j++) c[i][j] = 0.f;

    const uint32_t aAh = smem_u32(sAh);
    const uint32_t aAl = smem_u32(sAl);
    const uint32_t aBh = smem_u32(sBh[wn]);
    const uint32_t aBl = smem_u32(sBl[wn]);

    #pragma unroll
    for (int khalf = 0; khalf < 2; ++khalf) {
        __syncthreads();
        // ---- stage A half: 64 rows x 64 k, hi/lo ---------------------------
        {
            int r  = tid >> 2;
            int kc = (tid & 3) * 16;          // element offset within half
            const float* ap = A + (size_t)(m0 + r) * 128 + khalf * 64 + kc;
            #pragma unroll
            for (int j = 0; j < 8; j++) {
                float2 v = *(const float2*)(ap + 2 * j);
                float h0 = bfr(v.x), h1 = bfr(v.y);
                uint32_t b  = (uint32_t)(kc * 2 + j * 4);
                uint32_t pb = (uint32_t)(r * 128) + ((((b >> 4) ^ (r & 7)) << 4) | (b & 15));
                *(uint32_t*)(sAh + pb) = pack_bf16x2(h0, h1);
                *(uint32_t*)(sAl + pb) = pack_bf16x2(v.x - h0, v.y - h1);
            }
        }
        // ---- stage B half: 2 n-halves x 64 k-rows x 64 n, hi/lo ------------
        {
            int rr = tid >> 1;                 // 0..127
            int nh = rr >> 6, kr = rr & 63;
            int nc = (tid & 1) * 32;           // element offset within n-half
            const float* bp = Bw + (size_t)(khalf * 64 + kr) * N + n0 + nh * 64 + nc;
            uint8_t* dh = sBh[nh]; uint8_t* dl = sBl[nh];
            #pragma unroll
            for (int j = 0; j < 16; j++) {
                float2 v = *(const float2*)(bp + 2 * j);
                float h0 = bfr(v.x), h1 = bfr(v.y);
                uint32_t b  = (uint32_t)(nc * 2 + j * 4);
                uint32_t pb = (uint32_t)(kr * 128) + ((((b >> 4) ^ (kr & 7)) << 4) | (b & 15));
                *(uint32_t*)(dh + pb) = pack_bf16x2(h0, h1);
                *(uint32_t*)(dl + pb) = pack_bf16x2(v.x - h0, v.y - h1);
            }
        }
        __syncthreads();

        #pragma unroll
        for (int s = 0; s < 4; ++s) {
            // A fragments (m16 x k16), canonical row-major pattern
            uint32_t ah[4], al[4];
            {
                int row = wm * 16 + lr16;
                uint32_t off = (uint32_t)(row * 128) + ((((uint32_t)(s * 2 + lclog) ^ (row & 7)) << 4));
                ldm_x4(ah, aAh + off);
                ldm_x4(al, aAl + off);
            }
            // B fragments per n16 group, trans pattern (validated = attn V)
            int rowB = s * 16 + ((lm & 1) << 3) + lr;
            uint32_t rbase = (uint32_t)(rowB * 128);
            #pragma unroll
            for (int g = 0; g < 4; ++g) {
                uint32_t chunk = (uint32_t)(g * 2 + (lm >> 1));
                uint32_t off = rbase + ((chunk ^ (rowB & 7)) << 4);
                uint32_t bh[4], bl[4];
                ldm_x4_t(bh, aBh + off);
                ldm_x4_t(bl, aBl + off);
                mma_bf16(c[g*2],   ah, bh[0], bh[1]);
                mma_bf16(c[g*2],   ah, bl[0], bl[1]);
                mma_bf16(c[g*2],   al, bh[0], bh[1]);
                mma_bf16(c[g*2+1], ah, bh[2], bh[3]);
                mma_bf16(c[g*2+1], ah, bl[2], bl[3]);
                mma_bf16(c[g*2+1], al, bh[2], bh[3]);
            }
        }
    }

    // ---- epilogue: bias (+relu) --------------------------------------------
    const int rowA = m0 + wm * 16 + rq;
    #pragma unroll
    for (int t8 = 0; t8 < 8; ++t8) {
        int col = n0 + wn * 64 + t8 * 8 + d0;
        float b0 = bias[col], b1 = bias[col + 1];
        float v00 = c[t8][0] + b0, v01 = c[t8][1] + b1;
        float v10 = c[t8][2] + b0, v11 = c[t8][3] + b1;
        if (relu) {
            v00 = fmaxf(v00, 0.f); v01 = fmaxf(v01, 0.f);
            v10 = fmaxf(v10, 0.f); v11 = fmaxf(v11, 0.f);
        }
        *(float2*)(C + (size_t)rowA * N + col)       = make_float2(v00, v01);
        *(float2*)(C + (size_t)(rowA + 8) * N + col) = make_float2(v10, v11);
    }
}

// ================= HMMA flash attention (256-query tiles) ==================
#define KROWB 48
#define NT 4

__global__ __launch_bounds__(128) void attn_mma_kernel(float* __restrict__ ctx)
{
    __shared__ __align__(16) uint8_t sKh[128 * KROWB];
    __shared__ __align__(16) uint8_t sKl[128 * KROWB];
    __shared__ __align__(16) uint8_t sVh[128 * KROWB];
    __shared__ __align__(16) uint8_t sVl[128 * KROWB];

    const int tid  = threadIdx.x;
    const int lane = tid & 31;
    const int w    = tid >> 5;
    const int b    = blockIdx.y >> 3;
    const int h    = blockIdx.y & 7;
    const int q0   = blockIdx.x << 8;     // 256 queries per block

    const int rq = lane >> 2;
    const int d0 = (lane & 3) * 2;

    const float qscale = 0.25f * 1.44269504088896f;

    // ---- Q fragments (hi/lo bf16 split) ------------------------------------
    uint32_t ah[NT][4], al[NT][4];
    #pragma unroll
    for (int t = 0; t < NT; t++) {
        int rowA = q0 + w * 64 + t * 16 + rq;
        const float* qb = g_qkv + (size_t)(b * L_ + rowA) * (3 * D_) + h * HD_;
        float2 e0 = *(const float2*)(qb + d0);
        float2 e1 = *(const float2*)(qb + (size_t)8 * (3 * D_) + d0);
        float2 e2 = *(const float2*)(qb + d0 + 8);
        float2 e3 = *(const float2*)(qb + (size_t)8 * (3 * D_) + d0 + 8);
        float v[8] = {e0.x * qscale, e0.y * qscale, e1.x * qscale, e1.y * qscale,
                      e2.x * qscale, e2.y * qscale, e3.x * qscale, e3.y * qscale};
        #pragma unroll
        for (int j = 0; j < 4; j++) {
            float hx = bfr(v[2*j]), hy = bfr(v[2*j+1]);
            ah[t][j] = pack_bf16x2(hx, hy);
            al[t][j] = pack_bf16x2(v[2*j] - hx, v[2*j+1] - hy);
        }
    }

    const unsigned char* mA[NT];
    const unsigned char* mB[NT];
    #pragma unroll
    for (int t = 0; t < NT; t++) {
        mA[t] = g_mask8 + ((size_t)(b * L_ + q0 + w * 64 + t * 16 + rq)) * L_;
        mB[t] = mA[t] + (size_t)8 * L_;
    }

    const int lm = lane >> 3, lr = lane & 7;
    const uint32_t kOff = (uint32_t)((((lm >> 1) << 3) + lr) * KROWB + ((lm & 1) << 4));
    const uint32_t vOff = (uint32_t)((((lm & 1) << 3) + lr) * KROWB + ((lm >> 1) << 4));
    const uint32_t aKh = smem_u32(sKh) + kOff;
    const uint32_t aKl = smem_u32(sKl) + kOff;
    const uint32_t aVh = smem_u32(sVh) + vOff;
    const uint32_t aVl = smem_u32(sVl) + vOff;

    float o[NT][2][4];
    #pragma unroll
    for (int t = 0; t < NT; t++)
        #pragma unroll
        for (int n = 0; n < 2; n++)
            #pragma unroll
            for (int i = 0; i < 4; i++) o[t][n][i] = 0.f;
    float lA[NT], lB[NT];
    #pragma unroll
    for (int t = 0; t < NT; t++) { lA[t] = 0.f; lB[t] = 0.f; }

    for (int ck = 0; ck < L_ / 128; ++ck) {
        const int c0 = ck << 7;

        __syncthreads();
        {
            const float* kb = g_qkv + (size_t)(b * L_ + c0 + tid) * (3 * D_) + D_ + h * HD_;
            const float* vb = kb + D_;
            uint32_t* kh = (uint32_t*)(sKh + tid * KROWB);
            uint32_t* kl = (uint32_t*)(sKl + tid * KROWB);
            uint32_t* vh = (uint32_t*)(sVh + tid * KROWB);
            uint32_t* vl = (uint32_t*)(sVl + tid * KROWB);
            #pragma unroll
            for (int j = 0; j < 8; j++) {
                float2 kv = *(const float2*)(kb + 2 * j);
                float h0 = bfr(kv.x), h1 = bfr(kv.y);
                kh[j] = pack_bf16x2(h0, h1);
                kl[j] = pack_bf16x2(kv.x - h0, kv.y - h1);
                float2 vv = *(const float2*)(vb + 2 * j);
                float g0 = bfr(vv.x), g1 = bfr(vv.y);
                vh[j] = pack_bf16x2(g0, g1);
                vl[j] = pack_bf16x2(vv.x - g0, vv.y - g1);
            }
        }
        __syncthreads();

        #pragma unroll 2
        for (int s = 0; s < 8; ++s) {
            const uint32_t so = (uint32_t)(s * 16 * KROWB);
            uint32_t kh[4], kl[4], vh[4], vl[4];
            ldm_x4(kh, aKh + so);
            ldm_x4(kl, aKl + so);
            ldm_x4_t(vh, aVh + so);
            ldm_x4_t(vl, aVl + so);
            const int keyb = c0 + s * 16 + d0;

            #pragma unroll
            for (int t = 0; t < NT; t++) {
                float c0f[4] = {0.f, 0.f, 0.f, 0.f};
                float c1f[4] = {0.f, 0.f, 0.f, 0.f};
                mma_bf16(c0f, ah[t], kh[0], kh[1]);
                mma_bf16(c0f, ah[t], kl[0], kl[1]);
                mma_bf16(c0f, al[t], kh[0], kh[1]);
                mma_bf16(c1f, ah[t], kh[2], kh[3]);
                mma_bf16(c1f, ah[t], kl[2], kl[3]);
                mma_bf16(c1f, al[t], kh[2], kh[3]);

                uint16_t ma0 = *(const uint16_t*)(mA[t] + keyb);
                uint16_t mb0 = *(const uint16_t*)(mB[t] + keyb);
                uint16_t ma1 = *(const uint16_t*)(mA[t] + keyb + 8);
                uint16_t mb1 = *(const uint16_t*)(mB[t] + keyb + 8);

                float p00 = (ma0 & 0xFF) ? 0.f : ex2f(c0f[0]);
                float p01 = (ma0 >> 8)   ? 0.f : ex2f(c0f[1]);
                float p02 = (mb0 & 0xFF) ? 0.f : ex2f(c0f[2]);
                float p03 = (mb0 >> 8)   ? 0.f : ex2f(c0f[3]);
                float p10 = (ma1 & 0xFF) ? 0.f : ex2f(c1f[0]);
                float p11 = (ma1 >> 8)   ? 0.f : ex2f(c1f[1]);
                float p12 = (mb1 & 0xFF) ? 0.f : ex2f(c1f[2]);
                float p13 = (mb1 >> 8)   ? 0.f : ex2f(c1f[3]);

                uint32_t ap[4];
                ap[0] = pack_bf16x2(p00, p01);
                ap[1] = pack_bf16x2(p02, p03);
                ap[2] = pack_bf16x2(p10, p11);
                ap[3] = pack_bf16x2(p12, p13);

                lA[t] += lo16f(ap[0]) + hi16f(ap[0]) + lo16f(ap[2]) + hi16f(ap[2]);
                lB[t] += lo16f(ap[1]) + hi16f(ap[1]) + lo16f(ap[3]) + hi16f(ap[3]);

                mma_bf16(o[t][0], ap, vh[0], vh[1]);
                mma_bf16(o[t][0], ap, vl[0], vl[1]);
                mma_bf16(o[t][1], ap, vh[2], vh[3]);
                mma_bf16(o[t][1], ap, vl[2], vl[3]);
            }
        }
    }

    #pragma unroll
    for (int t = 0; t < NT; t++) {
        float la = lA[t];
        la += __shfl_xor_sync(0xffffffffu, la, 1);
        la += __shfl_xor_sync(0xffffffffu, la, 2);
        float lb = lB[t];
        lb += __shfl_xor_sync(0xffffffffu, lb, 1);
        lb += __shfl_xor_sync(0xffffffffu, lb, 2);
        float ia = (la > 0.f) ? (1.f / la) : 0.f;
        float ib = (lb > 0.f) ? (1.f / lb) : 0.f;

        int rowA = q0 + w * 64 + t * 16 + rq;
        float* oA = ctx + (size_t)(b * L_ + rowA) * D_ + h * HD_;
        float* oB = oA + (size_t)8 * D_;
        #pragma unroll
        for (int n = 0; n < 2; n++) {
            *(float2*)(oA + n * 8 + d0) = make_float2(o[t][n][0] * ia, o[t][n][1] * ia);
            *(float2*)(oB + n * 8 + d0) = make_float2(o[t][n][2] * ib, o[t][n][3] * ib);
        }
    }
}

// ---------------- fused residual add + LayerNorm ---------------------------
__global__ __launch_bounds__(128) void add_ln_kernel(
    const float* __restrict__ a, const float* __restrict__ r,
    const float* __restrict__ gamma, const float* __restrict__ beta,
    float* __restrict__ out)
{
    const int row = blockIdx.x;
    const int t = threadIdx.x;
    const int warp = t >> 5, lane = t & 31;
    __shared__ float red1[4], red2[4];

    float v = a[(size_t)row * D_ + t] + r[(size_t)row * D_ + t];

    float s = v;
    #pragma unroll
    for (int o = 16; o; o >>= 1) s += __shfl_xor_sync(0xffffffffu, s, o);
    if (lane == 0) red1[warp] = s;
    __syncthreads();
    float mu = (red1[0] + red1[1] + red1[2] + red1[3]) * (1.f / D_);

    float c = v - mu;
    float q = c * c;
    #pragma unroll
    for (int o = 16; o; o >>= 1) q += __shfl_xor_sync(0xffffffffu, q, o);
    if (lane == 0) red2[warp] = q;
    __syncthreads();
    float var = (red2[0] + red2[1] + red2[2] + red2[3]) * (1.f / D_);

    out[(size_t)row * D_ + t] = c * rsqrtf(var + LN_EPS) * gamma[t] + beta[t];
}

// ---------------- launch --------------------------------------------------
extern "C" void kernel_launch(void* const* d_in, const int* in_sizes, int n_in,
                              void* d_out, int out_size)
{
    const float* edge_x    = (const float*)d_in[0];
    const void*  edge_mask = d_in[1];
    const float* in_proj_w = (const float*)d_in[2];
    const float* in_proj_b = (const float*)d_in[3];
    const float* w1        = (const float*)d_in[4];
    const float* b1        = (const float*)d_in[5];
    const float* w2        = (const float*)d_in[6];
    const float* b2        = (const float*)d_in[7];
    const float* g1        = (const float*)d_in[8];
    const float* beta1     = (const float*)d_in[9];
    const float* g2        = (const float*)d_in[10];
    const float* beta2     = (const float*)d_in[11];
    float* out = (float*)d_out;

    void *p_qkv, *p_ctx, *p_x1, *p_ff1, *p_ff2;
    cudaGetSymbolAddress(&p_qkv, g_qkv);
    cudaGetSymbolAddress(&p_ctx, g_ctx);
    cudaGetSymbolAddress(&p_x1,  g_x1);
    cudaGetSymbolAddress(&p_ff1, g_ff1);
    cudaGetSymbolAddress(&p_ff2, g_ff2);

    const int nmask = B_ * L_ * L_;

    // 1) mask dtype detect + canonicalize to u8
    detect_mask_kernel<<<1, 32>>>((const unsigned char*)edge_mask);
    convert_mask_kernel<<<(nmask + 255) / 256, 256>>>(edge_mask, nmask);

    // 2) fused QKV projection: [16384,128] @ [128,384]  (HMMA)
    {
        dim3 grid(3 * D_ / 128, ROWS / 64);
        hmma_gemm_kernel<<<grid, 256>>>(edge_x, in_proj_w, in_proj_b,
                                        (float*)p_qkv, 3 * D_, 0);
    }

    // 3) masked attention -> ctx (HMMA flash, 256-q tiles)
    {
        dim3 grid(L_ / 256, B_ * H_);
        attn_mma_kernel<<<grid, 128>>>((float*)p_ctx);
    }

    // 4) x1 = LN(edge_x + ctx)
    add_ln_kernel<<<ROWS, 128>>>(edge_x, (const float*)p_ctx, g1, beta1, (float*)p_x1);

    // 5) ff1 = relu(x1 @ w1 + b1)  (HMMA)
    {
        dim3 grid(1, ROWS / 64);
        hmma_gemm_kernel<<<grid, 256>>>((const float*)p_x1, w1, b1,
                                        (float*)p_ff1, D_, 1);
    }
    // 6) ff2 = ff1 @ w2 + b2  (HMMA)
    {
        dim3 grid(1, ROWS / 64);
        hmma_gemm_kernel<<<grid, 256>>>((const float*)p_ff1, w2, b2,
                                        (float*)p_ff2, D_, 0);
    }
    // 7) out = LN(x1 + ff2)
    add_ln_kernel<<<ROWS, 128>>>((const float*)p_x1, (const float*)p_ff2, g2, beta2, out);
}

// round 5
// speedup vs baseline: 1.0497x; 1.0497x over previous
#include <cuda_runtime.h>
#include <cuda_bf16.h>
#include <math_constants.h>
#include <cstdint>

// Problem constants
#define B_   16
#define L_   1024
#define D_   128
#define H_   8
#define HD_  16
#define ROWS (B_ * L_)          // 16384
#define LN_EPS 1e-5f

// ---------------- scratch (device globals; no allocation allowed) ----------
__device__ float g_qkv[ROWS * 3 * D_];
__device__ float g_po0[ROWS * D_];      // attention partial O (keys 0..511)
__device__ float g_po1[ROWS * D_];      // attention partial O (keys 512..1023)
__device__ float g_pl [2 * ROWS * H_];  // partial l sums
__device__ float g_x1 [ROWS * D_];
__device__ float g_ff1[ROWS * D_];
__device__ float g_ff2[ROWS * D_];
__device__ unsigned char g_mask8[(size_t)B_ * L_ * L_];
__device__ int g_mask_is_i32;

// ============================ helpers ======================================
__device__ __forceinline__ uint32_t smem_u32(const void* p) {
    uint32_t a;
    asm("{ .reg .u64 t; cvta.to.shared.u64 t, %1; cvt.u32.u64 %0, t; }"
        : "=r"(a) : "l"(p));
    return a;
}
__device__ __forceinline__ uint32_t pack_bf16x2(float e, float o) {
    uint32_t r;
    asm("cvt.rn.bf16x2.f32 %0, %1, %2;" : "=r"(r) : "f"(o), "f"(e));
    return r;
}
__device__ __forceinline__ float ex2f(float x) {
    float y; asm("ex2.approx.f32 %0, %1;" : "=f"(y) : "f"(x)); return y;
}
__device__ __forceinline__ float bfr(float x) {
    return __bfloat162float(__float2bfloat16_rn(x));
}
__device__ __forceinline__ float lo16f(uint32_t u) { return __uint_as_float(u << 16); }
__device__ __forceinline__ float hi16f(uint32_t u) { return __uint_as_float(u & 0xFFFF0000u); }

__device__ __forceinline__ void mma_bf16(float* c, const uint32_t* a, uint32_t b0, uint32_t b1) {
    asm volatile("mma.sync.aligned.m16n8k16.row.col.f32.bf16.bf16.f32 "
        "{%0,%1,%2,%3}, {%4,%5,%6,%7}, {%8,%9}, {%0,%1,%2,%3};"
        : "+f"(c[0]), "+f"(c[1]), "+f"(c[2]), "+f"(c[3])
        : "r"(a[0]), "r"(a[1]), "r"(a[2]), "r"(a[3]), "r"(b0), "r"(b1));
}
__device__ __forceinline__ void ldm_x4(uint32_t* r, uint32_t addr) {
    asm volatile("ldmatrix.sync.aligned.m8n8.x4.shared.b16 {%0,%1,%2,%3}, [%4];"
        : "=r"(r[0]), "=r"(r[1]), "=r"(r[2]), "=r"(r[3]) : "r"(addr));
}
__device__ __forceinline__ void ldm_x4_t(uint32_t* r, uint32_t addr) {
    asm volatile("ldmatrix.sync.aligned.m8n8.x4.trans.shared.b16 {%0,%1,%2,%3}, [%4];"
        : "=r"(r[0]), "=r"(r[1]), "=r"(r[2]), "=r"(r[3]) : "r"(addr));
}

// ---------------- mask dtype detection + canonicalization ------------------
__global__ void detect_mask_kernel(const unsigned char* __restrict__ m) {
    if (threadIdx.x == 0 && blockIdx.x == 0) {
        int i32like = 1;
        for (int i = 0; i < 4096; i += 4) {
            unsigned char b0 = m[i], b1 = m[i+1], b2 = m[i+2], b3 = m[i+3];
            if ((b1 | b2 | b3) != 0 || b0 > 1) { i32like = 0; break; }
        }
        g_mask_is_i32 = i32like;
    }
}
__global__ void convert_mask_kernel(const void* __restrict__ in, int n) {
    int i = blockIdx.x * blockDim.x + threadIdx.x;
    if (i >= n) return;
    unsigned char v;
    if (g_mask_is_i32) v = (((const int*)in)[i] != 0) ? 1 : 0;
    else               v = (((const unsigned char*)in)[i] != 0) ? 1 : 0;
    g_mask8[i] = v;
}

// ================= HMMA GEMM (BM=32, BN=128): C = A@B + bias (opt relu) ====
// A [M,128] fp32, B [128,N] fp32 row-major. 256 threads = 8 warps:
// wm = w&1 (m16 tile), wn = w>>1 (n32 group). 3-term hi/lo bf16 split.
__global__ __launch_bounds__(256) void hmma_gemm32_kernel(
    const float* __restrict__ A, const float* __restrict__ Bw,
    const float* __restrict__ bias, float* __restrict__ C,
    int N, int relu)
{
    __shared__ __align__(16) uint8_t sAh[32 * 128];
    __shared__ __align__(16) uint8_t sAl[32 * 128];
    __shared__ __align__(16) uint8_t sBh[2][64 * 128];
    __shared__ __align__(16) uint8_t sBl[2][64 * 128];

    const int tid  = threadIdx.x;
    const int lane = tid & 31;
    const int w    = tid >> 5;
    const int wm   = w & 1;
    const int wn   = w >> 1;          // 0..3: n32 group
    const int m0   = blockIdx.y * 32;
    const int n0   = blockIdx.x * 128;

    const int rq = lane >> 2;
    const int d0 = (lane & 3) * 2;
    const int lr16  = lane & 15;
    const int lclog = lane >> 4;
    const int lm = lane >> 3, lr = lane & 7;

    float c[4][4];
    #pragma unroll
    for (int i = 0; i < 4; i++)
        #pragma unroll
        for (int j = 0; j < 4; j++) c[i][j] = 0.f;

    const uint32_t aAh = smem_u32(sAh);
    const uint32_t aAl = smem_u32(sAl);
    const uint32_t aBh = smem_u32(sBh[wn >> 1]);
    const uint32_t aBl = smem_u32(sBl[wn >> 1]);

    #pragma unroll
    for (int khalf = 0; khalf < 2; ++khalf) {
        __syncthreads();
        // ---- stage A half: 32 rows x 64 k, hi/lo ---------------------------
        {
            int r  = tid >> 3;
            int kc = (tid & 7) * 8;
            const float* ap = A + (size_t)(m0 + r) * 128 + khalf * 64 + kc;
            #pragma unroll
            for (int j = 0; j < 4; j++) {
                float2 v = *(const float2*)(ap + 2 * j);
                float h0 = bfr(v.x), h1 = bfr(v.y);
                uint32_t b  = (uint32_t)(kc * 2 + j * 4);
                uint32_t pb = (uint32_t)(r * 128) + ((((b >> 4) ^ (r & 7)) << 4) | (b & 15));
                *(uint32_t*)(sAh + pb) = pack_bf16x2(h0, h1);
                *(uint32_t*)(sAl + pb) = pack_bf16x2(v.x - h0, v.y - h1);
            }
        }
        // ---- stage B half: 2 n-halves x 64 k-rows x 64 n, hi/lo ------------
        {
            int rr = tid >> 1;
            int nh = rr >> 6, kr = rr & 63;
            int nc = (tid & 1) * 32;
            const float* bp = Bw + (size_t)(khalf * 64 + kr) * N + n0 + nh * 64 + nc;
            uint8_t* dh = sBh[nh]; uint8_t* dl = sBl[nh];
            #pragma unroll
            for (int j = 0; j < 16; j++) {
                float2 v = *(const float2*)(bp + 2 * j);
                float h0 = bfr(v.x), h1 = bfr(v.y);
                uint32_t b  = (uint32_t)(nc * 2 + j * 4);
                uint32_t pb = (uint32_t)(kr * 128) + ((((b >> 4) ^ (kr & 7)) << 4) | (b & 15));
                *(uint32_t*)(dh + pb) = pack_bf16x2(h0, h1);
                *(uint32_t*)(dl + pb) = pack_bf16x2(v.x - h0, v.y - h1);
            }
        }
        __syncthreads();

        #pragma unroll
        for (int s = 0; s < 4; ++s) {
            uint32_t ah[4], al[4];
            {
                int row = wm * 16 + lr16;
                uint32_t off = (uint32_t)(row * 128) + ((((uint32_t)(s * 2 + lclog) ^ (row & 7)) << 4));
                ldm_x4(ah, aAh + off);
                ldm_x4(al, aAl + off);
            }
            int rowB = s * 16 + ((lm & 1) << 3) + lr;
            uint32_t rbase = (uint32_t)(rowB * 128);
            #pragma unroll
            for (int g = 0; g < 2; ++g) {
                uint32_t gg = (uint32_t)((wn & 1) * 2 + g);
                uint32_t chunk = gg * 2 + (uint32_t)(lm >> 1);
                uint32_t off = rbase + ((chunk ^ (rowB & 7)) << 4);
                uint32_t bh[4], bl[4];
                ldm_x4_t(bh, aBh + off);
                ldm_x4_t(bl, aBl + off);
                mma_bf16(c[g*2],   ah, bh[0], bh[1]);
                mma_bf16(c[g*2],   ah, bl[0], bl[1]);
                mma_bf16(c[g*2],   al, bh[0], bh[1]);
                mma_bf16(c[g*2+1], ah, bh[2], bh[3]);
                mma_bf16(c[g*2+1], ah, bl[2], bl[3]);
                mma_bf16(c[g*2+1], al, bh[2], bh[3]);
            }
        }
    }

    // ---- epilogue: bias (+relu) --------------------------------------------
    const int rowA = m0 + wm * 16 + rq;
    #pragma unroll
    for (int t8 = 0; t8 < 4; ++t8) {
        int col = n0 + wn * 32 + t8 * 8 + d0;
        float b0 = bias[col], b1 = bias[col + 1];
        float v00 = c[t8][0] + b0, v01 = c[t8][1] + b1;
        float v10 = c[t8][2] + b0, v11 = c[t8][3] + b1;
        if (relu) {
            v00 = fmaxf(v00, 0.f); v01 = fmaxf(v01, 0.f);
            v10 = fmaxf(v10, 0.f); v11 = fmaxf(v11, 0.f);
        }
        *(float2*)(C + (size_t)rowA * N + col)       = make_float2(v00, v01);
        *(float2*)(C + (size_t)(rowA + 8) * N + col) = make_float2(v10, v11);
    }
}

// ================= HMMA flash attention (key-split, partial outputs) =======
// Block = (b, h, 128-q tile, key-half z). 4 warps, NT=2 m16 tiles per warp.
// Writes UNNORMALIZED partial O (g_po0/g_po1) and row-sums l (g_pl).
#define KROWB 48

__global__ __launch_bounds__(128) void attn_mma_kernel(
    float* __restrict__ po0, float* __restrict__ po1, float* __restrict__ pl)
{
    __shared__ __align__(16) uint8_t sKh[128 * KROWB];
    __shared__ __align__(16) uint8_t sKl[128 * KROWB];
    __shared__ __align__(16) uint8_t sVh[128 * KROWB];

    const int tid  = threadIdx.x;
    const int lane = tid & 31;
    const int w    = tid >> 5;
    const int b    = blockIdx.y >> 3;
    const int h    = blockIdx.y & 7;
    const int q0   = blockIdx.x << 7;
    const int zz   = blockIdx.z;          // key half

    const int rq = lane >> 2;
    const int d0 = (lane & 3) * 2;

    const float qscale = 0.25f * 1.44269504088896f;

    // ---- Q fragments (hi/lo bf16 split) ------------------------------------
    uint32_t ah[2][4], al[2][4];
    #pragma unroll
    for (int t = 0; t < 2; t++) {
        int rowA = q0 + w * 32 + t * 16 + rq;
        const float* qb = g_qkv + (size_t)(b * L_ + rowA) * (3 * D_) + h * HD_;
        float2 e0 = *(const float2*)(qb + d0);
        float2 e1 = *(const float2*)(qb + (size_t)8 * (3 * D_) + d0);
        float2 e2 = *(const float2*)(qb + d0 + 8);
        float2 e3 = *(const float2*)(qb + (size_t)8 * (3 * D_) + d0 + 8);
        float v[8] = {e0.x * qscale, e0.y * qscale, e1.x * qscale, e1.y * qscale,
                      e2.x * qscale, e2.y * qscale, e3.x * qscale, e3.y * qscale};
        #pragma unroll
        for (int j = 0; j < 4; j++) {
            float hx = bfr(v[2*j]), hy = bfr(v[2*j+1]);
            ah[t][j] = pack_bf16x2(hx, hy);
            al[t][j] = pack_bf16x2(v[2*j] - hx, v[2*j+1] - hy);
        }
    }

    const unsigned char* mA[2];
    const unsigned char* mB[2];
    #pragma unroll
    for (int t = 0; t < 2; t++) {
        mA[t] = g_mask8 + ((size_t)(b * L_ + q0 + w * 32 + t * 16 + rq)) * L_;
        mB[t] = mA[t] + (size_t)8 * L_;
    }

    const int lm = lane >> 3, lr = lane & 7;
    const uint32_t kOff = (uint32_t)((((lm >> 1) << 3) + lr) * KROWB + ((lm & 1) << 4));
    const uint32_t vOff = (uint32_t)((((lm & 1) << 3) + lr) * KROWB + ((lm >> 1) << 4));
    const uint32_t aKh = smem_u32(sKh) + kOff;
    const uint32_t aKl = smem_u32(sKl) + kOff;
    const uint32_t aVh = smem_u32(sVh) + vOff;

    float o[2][2][4];
    #pragma unroll
    for (int t = 0; t < 2; t++)
        #pragma unroll
        for (int n = 0; n < 2; n++)
            #pragma unroll
            for (int i = 0; i < 4; i++) o[t][n][i] = 0.f;
    float lA[2] = {0.f, 0.f}, lB[2] = {0.f, 0.f};

    for (int ck = zz * 4; ck < zz * 4 + 4; ++ck) {
        const int c0 = ck << 7;

        __syncthreads();
        {
            const float* kb = g_qkv + (size_t)(b * L_ + c0 + tid) * (3 * D_) + D_ + h * HD_;
            const float* vb = kb + D_;
            uint32_t* kh = (uint32_t*)(sKh + tid * KROWB);
            uint32_t* kl = (uint32_t*)(sKl + tid * KROWB);
            uint32_t* vh = (uint32_t*)(sVh + tid * KROWB);
            #pragma unroll
            for (int j = 0; j < 8; j++) {
                float2 kv = *(const float2*)(kb + 2 * j);
                float h0 = bfr(kv.x), h1 = bfr(kv.y);
                kh[j] = pack_bf16x2(h0, h1);
                kl[j] = pack_bf16x2(kv.x - h0, kv.y - h1);
                float2 vv = *(const float2*)(vb + 2 * j);
                vh[j] = pack_bf16x2(bfr(vv.x), bfr(vv.y));
            }
        }
        __syncthreads();

        #pragma unroll 2
        for (int s = 0; s < 8; ++s) {
            const uint32_t so = (uint32_t)(s * 16 * KROWB);
            uint32_t kh[4], kl[4], vh[4];
            ldm_x4(kh, aKh + so);
            ldm_x4(kl, aKl + so);
            ldm_x4_t(vh, aVh + so);
            const int keyb = c0 + s * 16 + d0;

            #pragma unroll
            for (int t = 0; t < 2; t++) {
                float c0f[4] = {0.f, 0.f, 0.f, 0.f};
                float c1f[4] = {0.f, 0.f, 0.f, 0.f};
                mma_bf16(c0f, ah[t], kh[0], kh[1]);
                mma_bf16(c0f, ah[t], kl[0], kl[1]);
                mma_bf16(c0f, al[t], kh[0], kh[1]);
                mma_bf16(c1f, ah[t], kh[2], kh[3]);
                mma_bf16(c1f, ah[t], kl[2], kl[3]);
                mma_bf16(c1f, al[t], kh[2], kh[3]);

                uint16_t ma0 = *(const uint16_t*)(mA[t] + keyb);
                uint16_t mb0 = *(const uint16_t*)(mB[t] + keyb);
                uint16_t ma1 = *(const uint16_t*)(mA[t] + keyb + 8);
                uint16_t mb1 = *(const uint16_t*)(mB[t] + keyb + 8);

                float p00 = (ma0 & 0xFF) ? 0.f : ex2f(c0f[0]);
                float p01 = (ma0 >> 8)   ? 0.f : ex2f(c0f[1]);
                float p02 = (mb0 & 0xFF) ? 0.f : ex2f(c0f[2]);
                float p03 = (mb0 >> 8)   ? 0.f : ex2f(c0f[3]);
                float p10 = (ma1 & 0xFF) ? 0.f : ex2f(c1f[0]);
                float p11 = (ma1 >> 8)   ? 0.f : ex2f(c1f[1]);
                float p12 = (mb1 & 0xFF) ? 0.f : ex2f(c1f[2]);
                float p13 = (mb1 >> 8)   ? 0.f : ex2f(c1f[3]);

                uint32_t ap[4];
                ap[0] = pack_bf16x2(p00, p01);
                ap[1] = pack_bf16x2(p02, p03);
                ap[2] = pack_bf16x2(p10, p11);
                ap[3] = pack_bf16x2(p12, p13);

                lA[t] += lo16f(ap[0]) + hi16f(ap[0]) + lo16f(ap[2]) + hi16f(ap[2]);
                lB[t] += lo16f(ap[1]) + hi16f(ap[1]) + lo16f(ap[3]) + hi16f(ap[3]);

                mma_bf16(o[t][0], ap, vh[0], vh[1]);
                mma_bf16(o[t][1], ap, vh[2], vh[3]);
            }
        }
    }

    // ---- epilogue: write partial (unnormalized) O and l --------------------
    float* po = zz ? po1 : po0;
    #pragma unroll
    for (int t = 0; t < 2; t++) {
        float la = lA[t];
        la += __shfl_xor_sync(0xffffffffu, la, 1);
        la += __shfl_xor_sync(0xffffffffu, la, 2);
        float lb = lB[t];
        lb += __shfl_xor_sync(0xffffffffu, lb, 1);
        lb += __shfl_xor_sync(0xffffffffu, lb, 2);

        int rowA = q0 + w * 32 + t * 16 + rq;
        float* oA = po + (size_t)(b * L_ + rowA) * D_ + h * HD_;
        float* oB = oA + (size_t)8 * D_;
        #pragma unroll
        for (int n = 0; n < 2; n++) {
            *(float2*)(oA + n * 8 + d0) = make_float2(o[t][n][0], o[t][n][1]);
            *(float2*)(oB + n * 8 + d0) = make_float2(o[t][n][2], o[t][n][3]);
        }
        if ((lane & 3) == 0) {
            pl[(size_t)zz * ROWS * H_ + (size_t)(b * L_ + rowA) * H_ + h]     = la;
            pl[(size_t)zz * ROWS * H_ + (size_t)(b * L_ + rowA + 8) * H_ + h] = lb;
        }
    }
}

// ---------------- combine partials + residual add + LayerNorm --------------
__global__ __launch_bounds__(128) void combine_add_ln_kernel(
    const float* __restrict__ xin,
    const float* __restrict__ po0, const float* __restrict__ po1,
    const float* __restrict__ pl,
    const float* __restrict__ gamma, const float* __restrict__ beta,
    float* __restrict__ out)
{
    const int row = blockIdx.x;
    const int t = threadIdx.x;
    const int head = t >> 4;
    const int warp = t >> 5, lane = t & 31;
    __shared__ float red1[4], red2[4];

    float l = pl[(size_t)row * H_ + head] + pl[(size_t)ROWS * H_ + (size_t)row * H_ + head];
    float osum = po0[(size_t)row * D_ + t] + po1[(size_t)row * D_ + t];
    float v = xin[(size_t)row * D_ + t] + ((l > 0.f) ? (osum / l) : 0.f);

    float s = v;
    #pragma unroll
    for (int o = 16; o; o >>= 1) s += __shfl_xor_sync(0xffffffffu, s, o);
    if (lane == 0) red1[warp] = s;
    __syncthreads();
    float mu = (red1[0] + red1[1] + red1[2] + red1[3]) * (1.f / D_);

    float c = v - mu;
    float q = c * c;
    #pragma unroll
    for (int o = 16; o; o >>= 1) q += __shfl_xor_sync(0xffffffffu, q, o);
    if (lane == 0) red2[warp] = q;
    __syncthreads();
    float var = (red2[0] + red2[1] + red2[2] + red2[3]) * (1.f / D_);

    out[(size_t)row * D_ + t] = c * rsqrtf(var + LN_EPS) * gamma[t] + beta[t];
}

// ---------------- fused residual add + LayerNorm ---------------------------
__global__ __launch_bounds__(128) void add_ln_kernel(
    const float* __restrict__ a, const float* __restrict__ r,
    const float* __restrict__ gamma, const float* __restrict__ beta,
    float* __restrict__ out)
{
    const int row = blockIdx.x;
    const int t = threadIdx.x;
    const int warp = t >> 5, lane = t & 31;
    __shared__ float red1[4], red2[4];

    float v = a[(size_t)row * D_ + t] + r[(size_t)row * D_ + t];

    float s = v;
    #pragma unroll
    for (int o = 16; o; o >>= 1) s += __shfl_xor_sync(0xffffffffu, s, o);
    if (lane == 0) red1[warp] = s;
    __syncthreads();
    float mu = (red1[0] + red1[1] + red1[2] + red1[3]) * (1.f / D_);

    float c = v - mu;
    float q = c * c;
    #pragma unroll
    for (int o = 16; o; o >>= 1) q += __shfl_xor_sync(0xffffffffu, q, o);
    if (lane == 0) red2[warp] = q;
    __syncthreads();
    float var = (red2[0] + red2[1] + red2[2] + red2[3]) * (1.f / D_);

    out[(size_t)row * D_ + t] = c * rsqrtf(var + LN_EPS) * gamma[t] + beta[t];
}

// ---------------- launch --------------------------------------------------
extern "C" void kernel_launch(void* const* d_in, const int* in_sizes, int n_in,
                              void* d_out, int out_size)
{
    const float* edge_x    = (const float*)d_in[0];
    const void*  edge_mask = d_in[1];
    const float* in_proj_w = (const float*)d_in[2];
    const float* in_proj_b = (const float*)d_in[3];
    const float* w1        = (const float*)d_in[4];
    const float* b1        = (const float*)d_in[5];
    const float* w2        = (const float*)d_in[6];
    const float* b2        = (const float*)d_in[7];
    const float* g1        = (const float*)d_in[8];
    const float* beta1     = (const float*)d_in[9];
    const float* g2        = (const float*)d_in[10];
    const float* beta2     = (const float*)d_in[11];
    float* out = (float*)d_out;

    void *p_qkv, *p_po0, *p_po1, *p_pl, *p_x1, *p_ff1, *p_ff2;
    cudaGetSymbolAddress(&p_qkv, g_qkv);
    cudaGetSymbolAddress(&p_po0, g_po0);
    cudaGetSymbolAddress(&p_po1, g_po1);
    cudaGetSymbolAddress(&p_pl,  g_pl);
    cudaGetSymbolAddress(&p_x1,  g_x1);
    cudaGetSymbolAddress(&p_ff1, g_ff1);
    cudaGetSymbolAddress(&p_ff2, g_ff2);

    const int nmask = B_ * L_ * L_;

    // 1) mask dtype detect + canonicalize to u8
    detect_mask_kernel<<<1, 32>>>((const unsigned char*)edge_mask);
    convert_mask_kernel<<<(nmask + 255) / 256, 256>>>(edge_mask, nmask);

    // 2) fused QKV projection: [16384,128] @ [128,384]  (HMMA, BM=32)
    {
        dim3 grid(3 * D_ / 128, ROWS / 32);
        hmma_gemm32_kernel<<<grid, 256>>>(edge_x, in_proj_w, in_proj_b,
                                          (float*)p_qkv, 3 * D_, 0);
    }

    // 3) masked attention -> partial O, l (HMMA flash, key-split 2)
    {
        dim3 grid(L_ / 128, B_ * H_, 2);
        attn_mma_kernel<<<grid, 128>>>((float*)p_po0, (float*)p_po1, (float*)p_pl);
    }

    // 4) x1 = LN(edge_x + combine(O,l))
    combine_add_ln_kernel<<<ROWS, 128>>>(edge_x, (const float*)p_po0,
                                         (const float*)p_po1, (const float*)p_pl,
                                         g1, beta1, (float*)p_x1);

    // 5) ff1 = relu(x1 @ w1 + b1)  (HMMA, BM=32)
    {
        dim3 grid(1, ROWS / 32);
        hmma_gemm32_kernel<<<grid, 256>>>((const float*)p_x1, w1, b1,
                                          (float*)p_ff1, D_, 1);
    }
    // 6) ff2 = ff1 @ w2 + b2  (HMMA, BM=32)
    {
        dim3 grid(1, ROWS / 32);
        hmma_gemm32_kernel<<<grid, 256>>>((const float*)p_ff1, w2, b2,
                                          (float*)p_ff2, D_, 0);
    }
    // 7) out = LN(x1 + ff2)
    add_ln_kernel<<<ROWS, 128>>>((const float*)p_x1, (const float*)p_ff2, g2, beta2, out);
}

// round 6
// speedup vs baseline: 1.5284x; 1.4560x over previous
#include <cuda_runtime.h>
#include <cuda_bf16.h>
#include <math_constants.h>
#include <cstdint>

// Problem constants
#define B_   16
#define L_   1024
#define D_   128
#define H_   8
#define HD_  16
#define ROWS (B_ * L_)          // 16384
#define LN_EPS 1e-5f
#define NMASKW (B_ * L_ * L_ / 32)

// ---------------- scratch (device globals) ---------------------------------
__device__ float g_q  [ROWS * D_];                 // Q fp32 (head layout)
__device__ __nv_bfloat16 g_kh[ROWS * D_];          // K hi
__device__ __nv_bfloat16 g_kl[ROWS * D_];          // K lo
__device__ __nv_bfloat16 g_vh[ROWS * D_];          // V hi
__device__ __nv_bfloat16 g_xh[ROWS * D_];          // edge_x hi
__device__ __nv_bfloat16 g_xl[ROWS * D_];          // edge_x lo
__device__ __nv_bfloat16 g_wqh[D_ * 3 * D_];       // in_proj_w hi
__device__ __nv_bfloat16 g_wql[D_ * 3 * D_];
__device__ __nv_bfloat16 g_w1h[D_ * D_];
__device__ __nv_bfloat16 g_w1l[D_ * D_];
__device__ __nv_bfloat16 g_w2h[D_ * D_];
__device__ __nv_bfloat16 g_w2l[D_ * D_];
__device__ __nv_bfloat16 g_f1h[ROWS * D_];         // ff1 hi
__device__ __nv_bfloat16 g_f1l[ROWS * D_];
__device__ __nv_bfloat16 g_x1h[ROWS * D_];         // x1 hi
__device__ __nv_bfloat16 g_x1l[ROWS * D_];
__device__ float g_po0[ROWS * D_];
__device__ float g_po1[ROWS * D_];
__device__ float g_pl [2 * ROWS * H_];
__device__ float g_x1 [ROWS * D_];
__device__ float g_ff2[ROWS * D_];
__device__ uint32_t g_maskbits[NMASKW];            // 2 MB
__device__ int g_mask_is_i32;

// ============================ helpers ======================================
__device__ __forceinline__ uint32_t smem_u32(const void* p) {
    uint32_t a;
    asm("{ .reg .u64 t; cvta.to.shared.u64 t, %1; cvt.u32.u64 %0, t; }"
        : "=r"(a) : "l"(p));
    return a;
}
__device__ __forceinline__ uint32_t pack_bf16x2(float e, float o) {
    uint32_t r;
    asm("cvt.rn.bf16x2.f32 %0, %1, %2;" : "=r"(r) : "f"(o), "f"(e));
    return r;
}
__device__ __forceinline__ float ex2f(float x) {
    float y; asm("ex2.approx.f32 %0, %1;" : "=f"(y) : "f"(x)); return y;
}
__device__ __forceinline__ float bfr(float x) {
    return __bfloat162float(__float2bfloat16_rn(x));
}
__device__ __forceinline__ void mma_bf16(float* c, const uint32_t* a, uint32_t b0, uint32_t b1) {
    asm volatile("mma.sync.aligned.m16n8k16.row.col.f32.bf16.bf16.f32 "
        "{%0,%1,%2,%3}, {%4,%5,%6,%7}, {%8,%9}, {%0,%1,%2,%3};"
        : "+f"(c[0]), "+f"(c[1]), "+f"(c[2]), "+f"(c[3])
        : "r"(a[0]), "r"(a[1]), "r"(a[2]), "r"(a[3]), "r"(b0), "r"(b1));
}
__device__ __forceinline__ void ldm_x4(uint32_t* r, uint32_t addr) {
    asm volatile("ldmatrix.sync.aligned.m8n8.x4.shared.b16 {%0,%1,%2,%3}, [%4];"
        : "=r"(r[0]), "=r"(r[1]), "=r"(r[2]), "=r"(r[3]) : "r"(addr));
}
__device__ __forceinline__ void ldm_x4_t(uint32_t* r, uint32_t addr) {
    asm volatile("ldmatrix.sync.aligned.m8n8.x4.trans.shared.b16 {%0,%1,%2,%3}, [%4];"
        : "=r"(r[0]), "=r"(r[1]), "=r"(r[2]), "=r"(r[3]) : "r"(addr));
}
#define ONES2 0x3F803F80u

// ---------------- mask detect + bitpack + fp32->bf16 hi/lo conv ------------
__global__ void detect_mask_kernel(const unsigned char* __restrict__ m) {
    if (threadIdx.x == 0 && blockIdx.x == 0) {
        int i32like = 1;
        for (int i = 0; i < 4096; i += 4) {
            unsigned char b0 = m[i], b1 = m[i+1], b2 = m[i+2], b3 = m[i+3];
            if ((b1 | b2 | b3) != 0 || b0 > 1) { i32like = 0; break; }
        }
        g_mask_is_i32 = i32like;
    }
}
__global__ void maskbits_kernel(const void* __restrict__ in) {
    int wIdx = blockIdx.x * blockDim.x + threadIdx.x;
    if (wIdx >= NMASKW) return;
    uint32_t bits = 0;
    if (g_mask_is_i32) {
        const int* p = (const int*)in + (size_t)wIdx * 32;
        #pragma unroll
        for (int j = 0; j < 32; j++) bits |= (p[j] != 0 ? 1u : 0u) << j;
    } else {
        const uint4* p = (const uint4*)((const uint8_t*)in + (size_t)wIdx * 32);
        uint4 a = p[0], bq = p[1];
        uint32_t ww[8] = {a.x, a.y, a.z, a.w, bq.x, bq.y, bq.z, bq.w};
        #pragma unroll
        for (int u = 0; u < 8; u++)
            #pragma unroll
            for (int j = 0; j < 4; j++)
                bits |= (((ww[u] >> (8 * j)) & 0xFFu) ? 1u : 0u) << (u * 4 + j);
    }
    g_maskbits[wIdx] = bits;
}
__global__ void conv_kernel(const float* __restrict__ src,
                            __nv_bfloat16* __restrict__ dh,
                            __nv_bfloat16* __restrict__ dl, int n) {
    int i = blockIdx.x * blockDim.x + threadIdx.x;
    if (i >= n) return;
    float f = src[i];
    float h = bfr(f);
    dh[i] = __float2bfloat16_rn(h);
    dl[i] = __float2bfloat16_rn(f - h);
}

// ================= HMMA GEMM (pre-converted bf16 planes) ===================
// A planes [M,128] bf16, B planes [128,N] bf16 row-major. BM=64, BN=128,
// 256 threads = 8 warps (wm = w&3 m16 tile, wn = w>>2 n64 half).
// mode 0: Cf = A@B + bias (fp32)
// mode 1: relu(A@B + bias) -> Ch/Cl bf16 planes (N must be 128)
// mode 2: QKV: n0==0 -> Cf (fp32 Q); n0==128 -> Ch/Cl (K hi/lo); n0==256 -> Cv (V hi)
__global__ __launch_bounds__(256) void hmma_gemm_pre(
    const __nv_bfloat16* __restrict__ Ah, const __nv_bfloat16* __restrict__ Al,
    const __nv_bfloat16* __restrict__ Bh, const __nv_bfloat16* __restrict__ Bl,
    const float* __restrict__ bias, int N, int mode,
    float* __restrict__ Cf,
    __nv_bfloat16* __restrict__ Ch, __nv_bfloat16* __restrict__ Cl,
    __nv_bfloat16* __restrict__ Cv)
{
    __shared__ __align__(16) uint8_t sAh[64 * 128];
    __shared__ __align__(16) uint8_t sAl[64 * 128];
    __shared__ __align__(16) uint8_t sBh[2][64 * 128];
    __shared__ __align__(16) uint8_t sBl[2][64 * 128];

    const int tid  = threadIdx.x;
    const int lane = tid & 31;
    const int w    = tid >> 5;
    const int wm   = w & 3;
    const int wn   = w >> 2;
    const int m0   = blockIdx.y * 64;
    const int n0   = blockIdx.x * 128;

    const int rq = lane >> 2;
    const int d0 = (lane & 3) * 2;
    const int lr16  = lane & 15;
    const int lclog = lane >> 4;
    const int lm = lane >> 3, lr = lane & 7;

    float c[8][4];
    #pragma unroll
    for (int i = 0; i < 8; i++)
        #pragma unroll
        for (int j = 0; j < 4; j++) c[i][j] = 0.f;

    const uint32_t aAh = smem_u32(sAh);
    const uint32_t aAl = smem_u32(sAl);
    const uint32_t aBh = smem_u32(sBh[wn]);
    const uint32_t aBl = smem_u32(sBl[wn]);

    #pragma unroll
    for (int khalf = 0; khalf < 2; ++khalf) {
        __syncthreads();
        // ---- stage A: 64 rows x 64 k, uint4 copies into swizzled layout ----
        #pragma unroll
        for (int rep = 0; rep < 2; ++rep) {
            int idx = rep * 256 + tid;
            int row = idx >> 3, chunk = idx & 7;
            uint32_t off = (uint32_t)(row * 128) + (((uint32_t)(chunk ^ (row & 7))) << 4);
            const uint4* sh = (const uint4*)(Ah + (size_t)(m0 + row) * 128 + khalf * 64);
            const uint4* sl = (const uint4*)(Al + (size_t)(m0 + row) * 128 + khalf * 64);
            *(uint4*)(sAh + off) = sh[chunk];
            *(uint4*)(sAl + off) = sl[chunk];
        }
        // ---- stage B: 2 n-halves x 64 k x 64 n ------------------------------
        #pragma unroll
        for (int rep = 0; rep < 4; ++rep) {
            int idx = rep * 256 + tid;
            int nh = idx >> 9, kr = (idx >> 3) & 63, chunk = idx & 7;
            uint32_t off = (uint32_t)(kr * 128) + (((uint32_t)(chunk ^ (kr & 7))) << 4);
            const uint4* sh = (const uint4*)(Bh + (size_t)(khalf * 64 + kr) * N + n0 + nh * 64);
            const uint4* sl = (const uint4*)(Bl + (size_t)(khalf * 64 + kr) * N + n0 + nh * 64);
            *(uint4*)(sBh[nh] + off) = sh[chunk];
            *(uint4*)(sBl[nh] + off) = sl[chunk];
        }
        __syncthreads();

        #pragma unroll
        for (int s = 0; s < 4; ++s) {
            uint32_t ah[4], al[4];
            {
                int row = wm * 16 + lr16;
                uint32_t off = (uint32_t)(row * 128) + ((((uint32_t)(s * 2 + lclog) ^ (row & 7)) << 4));
                ldm_x4(ah, aAh + off);
                ldm_x4(al, aAl + off);
            }
            int rowB = s * 16 + ((lm & 1) << 3) + lr;
            uint32_t rbase = (uint32_t)(rowB * 128);
            #pragma unroll
            for (int g = 0; g < 4; ++g) {
                uint32_t chunk = (uint32_t)(g * 2 + (lm >> 1));
                uint32_t off = rbase + ((chunk ^ (rowB & 7)) << 4);
                uint32_t bh[4], bl[4];
                ldm_x4_t(bh, aBh + off);
                ldm_x4_t(bl, aBl + off);
                mma_bf16(c[g*2],   ah, bh[0], bh[1]);
                mma_bf16(c[g*2],   ah, bl[0], bl[1]);
                mma_bf16(c[g*2],   al, bh[0], bh[1]);
                mma_bf16(c[g*2+1], ah, bh[2], bh[3]);
                mma_bf16(c[g*2+1], ah, bl[2], bl[3]);
                mma_bf16(c[g*2+1], al, bh[2], bh[3]);
            }
        }
    }

    // ---- epilogue -----------------------------------------------------------
    const int rowA = m0 + wm * 16 + rq;
    #pragma unroll
    for (int t8 = 0; t8 < 8; ++t8) {
        int col = n0 + wn * 64 + t8 * 8 + d0;
        float b0 = bias[col], b1 = bias[col + 1];
        float v00 = c[t8][0] + b0, v01 = c[t8][1] + b1;
        float v10 = c[t8][2] + b0, v11 = c[t8][3] + b1;

        if (mode == 0) {
            *(float2*)(Cf + (size_t)rowA * N + col)       = make_float2(v00, v01);
            *(float2*)(Cf + (size_t)(rowA + 8) * N + col) = make_float2(v10, v11);
        } else if (mode == 1) {
            v00 = fmaxf(v00, 0.f); v01 = fmaxf(v01, 0.f);
            v10 = fmaxf(v10, 0.f); v11 = fmaxf(v11, 0.f);
            float h00 = bfr(v00), h01 = bfr(v01), h10 = bfr(v10), h11 = bfr(v11);
            ((uint32_t*)Ch)[((size_t)rowA * 128 + col) >> 1]       = pack_bf16x2(h00, h01);
            ((uint32_t*)Cl)[((size_t)rowA * 128 + col) >> 1]       = pack_bf16x2(v00 - h00, v01 - h01);
            ((uint32_t*)Ch)[((size_t)(rowA + 8) * 128 + col) >> 1] = pack_bf16x2(h10, h11);
            ((uint32_t*)Cl)[((size_t)(rowA + 8) * 128 + col) >> 1] = pack_bf16x2(v10 - h10, v11 - h11);
        } else {
            if (n0 == 0) {
                *(float2*)(Cf + (size_t)rowA * 128 + col)       = make_float2(v00, v01);
                *(float2*)(Cf + (size_t)(rowA + 8) * 128 + col) = make_float2(v10, v11);
            } else if (n0 == 128) {
                int kc = col - 128;
                float h00 = bfr(v00), h01 = bfr(v01), h10 = bfr(v10), h11 = bfr(v11);
                ((uint32_t*)Ch)[((size_t)rowA * 128 + kc) >> 1]       = pack_bf16x2(h00, h01);
                ((uint32_t*)Cl)[((size_t)rowA * 128 + kc) >> 1]       = pack_bf16x2(v00 - h00, v01 - h01);
                ((uint32_t*)Ch)[((size_t)(rowA + 8) * 128 + kc) >> 1] = pack_bf16x2(h10, h11);
                ((uint32_t*)Cl)[((size_t)(rowA + 8) * 128 + kc) >> 1] = pack_bf16x2(v10 - h10, v11 - h11);
            } else {
                int vc = col - 256;
                ((uint32_t*)Cv)[((size_t)rowA * 128 + vc) >> 1]       = pack_bf16x2(bfr(v00), bfr(v01));
                ((uint32_t*)Cv)[((size_t)(rowA + 8) * 128 + vc) >> 1] = pack_bf16x2(bfr(v10), bfr(v11));
            }
        }
    }
}

// ================= HMMA flash attention (key-split, bf16 planes) ===========
#define KROWB 48

__global__ __launch_bounds__(128) void attn_mma_kernel(
    float* __restrict__ po0, float* __restrict__ po1, float* __restrict__ pl)
{
    __shared__ __align__(16) uint8_t sKh[128 * KROWB];
    __shared__ __align__(16) uint8_t sKl[128 * KROWB];
    __shared__ __align__(16) uint8_t sVh[128 * KROWB];

    const int tid  = threadIdx.x;
    const int lane = tid & 31;
    const int w    = tid >> 5;
    const int b    = blockIdx.y >> 3;
    const int h    = blockIdx.y & 7;
    const int q0   = blockIdx.x << 7;
    const int zz   = blockIdx.z;

    const int rq = lane >> 2;
    const int d0 = (lane & 3) * 2;

    const float qscale = 0.25f * 1.44269504088896f;

    // ---- Q fragments (hi/lo bf16 split) from fp32 Q plane -------------------
    uint32_t ah[2][4], al[2][4];
    #pragma unroll
    for (int t = 0; t < 2; t++) {
        int rowA = q0 + w * 32 + t * 16 + rq;
        const float* qb = g_q + (size_t)(b * L_ + rowA) * D_ + h * HD_;
        float2 e0 = *(const float2*)(qb + d0);
        float2 e1 = *(const float2*)(qb + (size_t)8 * D_ + d0);
        float2 e2 = *(const float2*)(qb + d0 + 8);
        float2 e3 = *(const float2*)(qb + (size_t)8 * D_ + d0 + 8);
        float v[8] = {e0.x * qscale, e0.y * qscale, e1.x * qscale, e1.y * qscale,
                      e2.x * qscale, e2.y * qscale, e3.x * qscale, e3.y * qscale};
        #pragma unroll
        for (int j = 0; j < 4; j++) {
            float hx = bfr(v[2*j]), hy = bfr(v[2*j+1]);
            ah[t][j] = pack_bf16x2(hx, hy);
            al[t][j] = pack_bf16x2(v[2*j] - hx, v[2*j+1] - hy);
        }
    }

    // mask-bit row bases (uint4 index): row*8 words-of-16B
    const uint4* mbase = (const uint4*)g_maskbits;
    int mrowA[2], mrowB[2];
    #pragma unroll
    for (int t = 0; t < 2; t++) {
        mrowA[t] = (b * L_ + q0 + w * 32 + t * 16 + rq) * 8;
        mrowB[t] = mrowA[t] + 8 * 8;
    }

    const int lm = lane >> 3, lr = lane & 7;
    const uint32_t kOff = (uint32_t)((((lm >> 1) << 3) + lr) * KROWB + ((lm & 1) << 4));
    const uint32_t vOff = (uint32_t)((((lm & 1) << 3) + lr) * KROWB + ((lm >> 1) << 4));
    const uint32_t aKh = smem_u32(sKh) + kOff;
    const uint32_t aKl = smem_u32(sKl) + kOff;
    const uint32_t aVh = smem_u32(sVh) + vOff;

    float o[2][2][4];
    float lac[2][4];
    #pragma unroll
    for (int t = 0; t < 2; t++) {
        #pragma unroll
        for (int n = 0; n < 2; n++)
            #pragma unroll
            for (int i = 0; i < 4; i++) o[t][n][i] = 0.f;
        #pragma unroll
        for (int i = 0; i < 4; i++) lac[t][i] = 0.f;
    }

    for (int ck = zz * 4; ck < zz * 4 + 4; ++ck) {
        const int c0 = ck << 7;

        __syncthreads();
        // ---- stage K/V from bf16 planes: pure uint4 copies -------------------
        {
            const size_t src = (size_t)(b * L_ + c0 + tid) * D_ + h * HD_;
            const uint4* kh = (const uint4*)(g_kh + src);
            const uint4* kl = (const uint4*)(g_kl + src);
            const uint4* vh = (const uint4*)(g_vh + src);
            uint4* dkh = (uint4*)(sKh + tid * KROWB);
            uint4* dkl = (uint4*)(sKl + tid * KROWB);
            uint4* dvh = (uint4*)(sVh + tid * KROWB);
            dkh[0] = kh[0]; dkh[1] = kh[1];
            dkl[0] = kl[0]; dkl[1] = kl[1];
            dvh[0] = vh[0]; dvh[1] = vh[1];
        }
        __syncthreads();

        // mask bits for this chunk: 128 bits per row
        uint32_t mwa[2][4], mwb[2][4];
        #pragma unroll
        for (int t = 0; t < 2; t++) {
            uint4 a = mbase[mrowA[t] + (c0 >> 7)];
            uint4 bq = mbase[mrowB[t] + (c0 >> 7)];
            mwa[t][0] = a.x;  mwa[t][1] = a.y;  mwa[t][2] = a.z;  mwa[t][3] = a.w;
            mwb[t][0] = bq.x; mwb[t][1] = bq.y; mwb[t][2] = bq.z; mwb[t][3] = bq.w;
        }

        #pragma unroll 2
        for (int s = 0; s < 8; ++s) {
            const uint32_t so = (uint32_t)(s * 16 * KROWB);
            uint32_t kh[4], kl[4], vh[4];
            ldm_x4(kh, aKh + so);
            ldm_x4(kl, aKl + so);
            ldm_x4_t(vh, aVh + so);
            const int sh = ((s & 1) << 4) + d0;

            #pragma unroll
            for (int t = 0; t < 2; t++) {
                float c0f[4] = {0.f, 0.f, 0.f, 0.f};
                float c1f[4] = {0.f, 0.f, 0.f, 0.f};
                mma_bf16(c0f, ah[t], kh[0], kh[1]);
                mma_bf16(c0f, ah[t], kl[0], kl[1]);
                mma_bf16(c0f, al[t], kh[0], kh[1]);
                mma_bf16(c1f, ah[t], kh[2], kh[3]);
                mma_bf16(c1f, ah[t], kl[2], kl[3]);
                mma_bf16(c1f, al[t], kh[2], kh[3]);

                uint32_t wa = mwa[t][s >> 1] >> sh;
                uint32_t wb = mwb[t][s >> 1] >> sh;

                float p00 = (wa & 1u)     ? 0.f : ex2f(c0f[0]);
                float p01 = (wa & 2u)     ? 0.f : ex2f(c0f[1]);
                float p02 = (wb & 1u)     ? 0.f : ex2f(c0f[2]);
                float p03 = (wb & 2u)     ? 0.f : ex2f(c0f[3]);
                float p10 = (wa & 0x100u) ? 0.f : ex2f(c1f[0]);
                float p11 = (wa & 0x200u) ? 0.f : ex2f(c1f[1]);
                float p12 = (wb & 0x100u) ? 0.f : ex2f(c1f[2]);
                float p13 = (wb & 0x200u) ? 0.f : ex2f(c1f[3]);

                uint32_t ap[4];
                ap[0] = pack_bf16x2(p00, p01);
                ap[1] = pack_bf16x2(p02, p03);
                ap[2] = pack_bf16x2(p10, p11);
                ap[3] = pack_bf16x2(p12, p13);

                mma_bf16(o[t][0], ap, vh[0], vh[1]);
                mma_bf16(o[t][1], ap, vh[2], vh[3]);
                mma_bf16(lac[t], ap, ONES2, ONES2);   // row-sum of P via ones-column
            }
        }
    }

    // ---- epilogue: write partial O and l ------------------------------------
    float* po = zz ? po1 : po0;
    #pragma unroll
    for (int t = 0; t < 2; t++) {
        int rowA = q0 + w * 32 + t * 16 + rq;
        float* oA = po + (size_t)(b * L_ + rowA) * D_ + h * HD_;
        float* oB = oA + (size_t)8 * D_;
        #pragma unroll
        for (int n = 0; n < 2; n++) {
            *(float2*)(oA + n * 8 + d0) = make_float2(o[t][n][0], o[t][n][1]);
            *(float2*)(oB + n * 8 + d0) = make_float2(o[t][n][2], o[t][n][3]);
        }
        if ((lane & 3) == 0) {
            pl[(size_t)zz * ROWS * H_ + (size_t)(b * L_ + rowA) * H_ + h]     = lac[t][0];
            pl[(size_t)zz * ROWS * H_ + (size_t)(b * L_ + rowA + 8) * H_ + h] = lac[t][2];
        }
    }
}

// ---------------- combine partials + residual add + LayerNorm --------------
// also emits x1 hi/lo bf16 planes for the FF GEMM
__global__ __launch_bounds__(128) void combine_add_ln_kernel(
    const float* __restrict__ xin,
    const float* __restrict__ po0, const float* __restrict__ po1,
    const float* __restrict__ pl,
    const float* __restrict__ gamma, const float* __restrict__ beta,
    float* __restrict__ out,
    __nv_bfloat16* __restrict__ oh, __nv_bfloat16* __restrict__ ol)
{
    const int row = blockIdx.x;
    const int t = threadIdx.x;
    const int head = t >> 4;
    const int warp = t >> 5, lane = t & 31;
    __shared__ float red1[4], red2[4];

    float l = pl[(size_t)row * H_ + head] + pl[(size_t)ROWS * H_ + (size_t)row * H_ + head];
    float osum = po0[(size_t)row * D_ + t] + po1[(size_t)row * D_ + t];
    float v = xin[(size_t)row * D_ + t] + ((l > 0.f) ? (osum / l) : 0.f);

    float s = v;
    #pragma unroll
    for (int o = 16; o; o >>= 1) s += __shfl_xor_sync(0xffffffffu, s, o);
    if (lane == 0) red1[warp] = s;
    __syncthreads();
    float mu = (red1[0] + red1[1] + red1[2] + red1[3]) * (1.f / D_);

    float c = v - mu;
    float q = c * c;
    #pragma unroll
    for (int o = 16; o; o >>= 1) q += __shfl_xor_sync(0xffffffffu, q, o);
    if (lane == 0) red2[warp] = q;
    __syncthreads();
    float var = (red2[0] + red2[1] + red2[2] + red2[3]) * (1.f / D_);

    float y = c * rsqrtf(var + LN_EPS) * gamma[t] + beta[t];
    out[(size_t)row * D_ + t] = y;
    float hy = bfr(y);
    oh[(size_t)row * D_ + t] = __float2bfloat16_rn(hy);
    ol[(size_t)row * D_ + t] = __float2bfloat16_rn(y - hy);
}

// ---------------- fused residual add + LayerNorm ---------------------------
__global__ __launch_bounds__(128) void add_ln_kernel(
    const float* __restrict__ a, const float* __restrict__ r,
    const float* __restrict__ gamma, const float* __restrict__ beta,
    float* __restrict__ out)
{
    const int row = blockIdx.x;
    const int t = threadIdx.x;
    const int warp = t >> 5, lane = t & 31;
    __shared__ float red1[4], red2[4];

    float v = a[(size_t)row * D_ + t] + r[(size_t)row * D_ + t];

    float s = v;
    #pragma unroll
    for (int o = 16; o; o >>= 1) s += __shfl_xor_sync(0xffffffffu, s, o);
    if (lane == 0) red1[warp] = s;
    __syncthreads();
    float mu = (red1[0] + red1[1] + red1[2] + red1[3]) * (1.f / D_);

    float c = v - mu;
    float q = c * c;
    #pragma unroll
    for (int o = 16; o; o >>= 1) q += __shfl_xor_sync(0xffffffffu, q, o);
    if (lane == 0) red2[warp] = q;
    __syncthreads();
    float var = (red2[0] + red2[1] + red2[2] + red2[3]) * (1.f / D_);

    out[(size_t)row * D_ + t] = c * rsqrtf(var + LN_EPS) * gamma[t] + beta[t];
}

// ---------------- launch --------------------------------------------------
extern "C" void kernel_launch(void* const* d_in, const int* in_sizes, int n_in,
                              void* d_out, int out_size)
{
    const float* edge_x    = (const float*)d_in[0];
    const void*  edge_mask = d_in[1];
    const float* in_proj_w = (const float*)d_in[2];
    const float* in_proj_b = (const float*)d_in[3];
    const float* w1        = (const float*)d_in[4];
    const float* b1        = (const float*)d_in[5];
    const float* w2        = (const float*)d_in[6];
    const float* b2        = (const float*)d_in[7];
    const float* g1        = (const float*)d_in[8];
    const float* beta1     = (const float*)d_in[9];
    const float* g2        = (const float*)d_in[10];
    const float* beta2     = (const float*)d_in[11];
    float* out = (float*)d_out;

    void *p_q, *p_kh, *p_kl, *p_vh, *p_xh, *p_xl;
    void *p_wqh, *p_wql, *p_w1h, *p_w1l, *p_w2h, *p_w2l;
    void *p_f1h, *p_f1l, *p_x1h, *p_x1l;
    void *p_po0, *p_po1, *p_pl, *p_x1, *p_ff2;
    cudaGetSymbolAddress(&p_q,   g_q);
    cudaGetSymbolAddress(&p_kh,  g_kh);
    cudaGetSymbolAddress(&p_kl,  g_kl);
    cudaGetSymbolAddress(&p_vh,  g_vh);
    cudaGetSymbolAddress(&p_xh,  g_xh);
    cudaGetSymbolAddress(&p_xl,  g_xl);
    cudaGetSymbolAddress(&p_wqh, g_wqh);
    cudaGetSymbolAddress(&p_wql, g_wql);
    cudaGetSymbolAddress(&p_w1h, g_w1h);
    cudaGetSymbolAddress(&p_w1l, g_w1l);
    cudaGetSymbolAddress(&p_w2h, g_w2h);
    cudaGetSymbolAddress(&p_w2l, g_w2l);
    cudaGetSymbolAddress(&p_f1h, g_f1h);
    cudaGetSymbolAddress(&p_f1l, g_f1l);
    cudaGetSymbolAddress(&p_x1h, g_x1h);
    cudaGetSymbolAddress(&p_x1l, g_x1l);
    cudaGetSymbolAddress(&p_po0, g_po0);
    cudaGetSymbolAddress(&p_po1, g_po1);
    cudaGetSymbolAddress(&p_pl,  g_pl);
    cudaGetSymbolAddress(&p_x1,  g_x1);
    cudaGetSymbolAddress(&p_ff2, g_ff2);

    // 1) mask detect + bitpack
    detect_mask_kernel<<<1, 32>>>((const unsigned char*)edge_mask);
    maskbits_kernel<<<NMASKW / 256, 256>>>(edge_mask);

    // 2) pre-convert inputs/weights to bf16 hi/lo planes
    conv_kernel<<<ROWS * D_ / 256, 256>>>(edge_x, (__nv_bfloat16*)p_xh, (__nv_bfloat16*)p_xl, ROWS * D_);
    conv_kernel<<<(D_ * 3 * D_) / 256, 256>>>(in_proj_w, (__nv_bfloat16*)p_wqh, (__nv_bfloat16*)p_wql, D_ * 3 * D_);
    conv_kernel<<<(D_ * D_) / 256, 256>>>(w1, (__nv_bfloat16*)p_w1h, (__nv_bfloat16*)p_w1l, D_ * D_);
    conv_kernel<<<(D_ * D_) / 256, 256>>>(w2, (__nv_bfloat16*)p_w2h, (__nv_bfloat16*)p_w2l, D_ * D_);

    // 3) QKV projection (mode 2): Q fp32, K hi/lo, V hi
    {
        dim3 grid(3, ROWS / 64);
        hmma_gemm_pre<<<grid, 256>>>((const __nv_bfloat16*)p_xh, (const __nv_bfloat16*)p_xl,
                                     (const __nv_bfloat16*)p_wqh, (const __nv_bfloat16*)p_wql,
                                     in_proj_b, 3 * D_, 2,
                                     (float*)p_q, (__nv_bfloat16*)p_kh, (__nv_bfloat16*)p_kl,
                                     (__nv_bfloat16*)p_vh);
    }

    // 4) masked attention -> partial O, l
    {
        dim3 grid(L_ / 128, B_ * H_, 2);
        attn_mma_kernel<<<grid, 128>>>((float*)p_po0, (float*)p_po1, (float*)p_pl);
    }

    // 5) x1 = LN(edge_x + combine(O,l)), emit fp32 + hi/lo planes
    combine_add_ln_kernel<<<ROWS, 128>>>(edge_x, (const float*)p_po0,
                                         (const float*)p_po1, (const float*)p_pl,
                                         g1, beta1, (float*)p_x1,
                                         (__nv_bfloat16*)p_x1h, (__nv_bfloat16*)p_x1l);

    // 6) ff1 = relu(x1 @ w1 + b1) -> hi/lo planes (mode 1)
    {
        dim3 grid(1, ROWS / 64);
        hmma_gemm_pre<<<grid, 256>>>((const __nv_bfloat16*)p_x1h, (const __nv_bfloat16*)p_x1l,
                                     (const __nv_bfloat16*)p_w1h, (const __nv_bfloat16*)p_w1l,
                                     b1, D_, 1,
                                     nullptr, (__nv_bfloat16*)p_f1h, (__nv_bfloat16*)p_f1l, nullptr);
    }
    // 7) ff2 = ff1 @ w2 + b2 (mode 0, fp32)
    {
        dim3 grid(1, ROWS / 64);
        hmma_gemm_pre<<<grid, 256>>>((const __nv_bfloat16*)p_f1h, (const __nv_bfloat16*)p_f1l,
                                     (const __nv_bfloat16*)p_w2h, (const __nv_bfloat16*)p_w2l,
                                     b2, D_, 0,
                                     (float*)p_ff2, nullptr, nullptr, nullptr);
    }
    // 8) out = LN(x1 + ff2)
    add_ln_kernel<<<ROWS, 128>>>((const float*)p_x1, (const float*)p_ff2, g2, beta2, out);
}